// round 16
// baseline (speedup 1.0000x reference)
#include <cuda_runtime.h>
#include <cstdint>

#define NU 400000
#define NN 600000
#define DV 16              // float4 words per row (D=64)
#define BATCH 8192
#define SEC (BATCH * DV)
#define STRIDE 32          // CSR slots per row (max degree ~16, 2x headroom)
#define FB_BLOCKS 296      // fused frontier kernel: 2 blocks/SM, always co-resident
#define FB_TPB 256

// ---- scratch (device globals; allocation is forbidden) ----
__device__ float g_bufA[(size_t)NN * 64];
__device__ float g_bufB[(size_t)NN * 64];
__device__ int2  g_scsr[(size_t)NN * STRIDE];   // strided CSR {col, val}
__device__ int   g_wpos[NN];                    // cursors; init r*STRIDE, end after scatter
__device__ int   g_sizes[NN];                   // per-row embedding size
__device__ int   g_lists[2 * NN];               // levels 1..2
// memset blob: [0,NN)=flags(uint) | +4 cnt | +1 barrier counter
#define CNT_OFF NN
#define BAR_OFF (NN + 4)
#define BLOB_INTS (NN + 5)
__device__ int   g_blob[BLOB_INTS];

// ================= per-row sizes from prefix masks (streaming, overlapped) =================
__global__ void sizes_k(const int4* __restrict__ um, const int4* __restrict__ im,
                        int* __restrict__ sizes) {
    int t = blockIdx.x * blockDim.x + threadIdx.x;
    if (t >= NN * DV) return;
    int r = t >> 4, lane = t & 15;
    int4 m = (r < NU) ? __ldg(um + r * DV + lane) : __ldg(im + (r - NU) * DV + lane);
    int s = m.x + m.y + m.z + m.w;
    s += __shfl_down_sync(0xffffffffu, s, 8, 16);
    s += __shfl_down_sync(0xffffffffu, s, 4, 16);
    s += __shfl_down_sync(0xffffffffu, s, 2, 16);
    s += __shfl_down_sync(0xffffffffu, s, 1, 16);
    if (lane == 0) sizes[r] = s;
}

// ============ output init: acc sections = masked source; ego = same (ILP-2) ============
__global__ void init_out_k(const float4* __restrict__ ue, const float4* __restrict__ ie,
                           const int4* __restrict__ um, const int4* __restrict__ im,
                           const int* __restrict__ users, const int* __restrict__ pos,
                           const int* __restrict__ neg, float4* __restrict__ out) {
    const int HALF = 3 * SEC / 2;
    int t = blockIdx.x * blockDim.x + threadIdx.x;
    if (t >= HALF) return;
#pragma unroll
    for (int u = 0; u < 2; u++) {
        int i = t + u * HALF;
        int sec = i / SEC;
        int rem = i - sec * SEC;
        int b = rem >> 4, lane = rem & 15;
        int row = (sec == 0) ? users[b] : (sec == 1 ? NU + pos[b] : NU + neg[b]);
        float4 e; int4 m;
        if (row < NU) { e = ue[row * DV + lane]; m = um[row * DV + lane]; }
        else          { int j = (row - NU) * DV + lane; e = ie[j]; m = im[j]; }
        float4 v;
        v.x = m.x ? e.x : 0.f;
        v.y = m.y ? e.y : 0.f;
        v.z = m.z ? e.z : 0.f;
        v.w = m.w ? e.w : 0.f;
        out[i] = v;
        out[3 * SEC + i] = v;
    }
}

// ============ software grid barrier (monotonic counter; reset by per-launch memset) ============
__device__ __forceinline__ void gbar(unsigned int* bar, unsigned int target) {
    __syncthreads();
    if (threadIdx.x == 0) {
        __threadfence();
        atomicAdd(bar, 1u);
        while (atomicAdd(bar, 0u) < target) { }
    }
    __syncthreads();
}

// ============ fused frontier pipeline: iota+seed | fpass 3->2 | fpass 2->1 | scatter+compact ============
__global__ void __launch_bounds__(FB_TPB, 2)
frontier_fused_k(const int4* __restrict__ r4, const int4* __restrict__ c4,
                 const float4* __restrict__ v4,
                 const int* __restrict__ r, const int* __restrict__ c,
                 const float* __restrict__ v,
                 const int* __restrict__ users, const int* __restrict__ pos,
                 const int* __restrict__ neg,
                 unsigned int* __restrict__ flags, int* __restrict__ wpos,
                 int2* __restrict__ csr, int* __restrict__ lists, int* __restrict__ cnt,
                 unsigned int* __restrict__ bar, int n4, int E) {
    int tid = blockIdx.x * blockDim.x + threadIdx.x;
    int NT = gridDim.x * blockDim.x;
    unsigned char* fb = (unsigned char*)flags;

    // ---- Phase 0: wpos iota + flag seed ----
    for (int i = tid; i < NN; i += NT) wpos[i] = i * STRIDE;
    for (int i = tid; i < 3 * BATCH; i += NT) {
        int b = i % BATCH, sec = i / BATCH;
        int row = (sec == 0) ? users[b] : (sec == 1 ? NU + pos[b] : NU + neg[b]);
        flags[row] = 0x01010100u;   // bytes 1,2,3 = levels 1,2,3
    }
    gbar(bar, FB_BLOCKS * 1);

    // ---- Phase 1 & 2: two symmetric frontier passes ----
#pragma unroll
    for (int pass = 0; pass < 2; pass++) {
        int inl = 3 - pass, outl = 2 - pass;
        for (int i = tid; i < n4; i += NT) {
            int4 rr = __ldg(r4 + i);
            int4 cc = __ldg(c4 + i);
            bool r0 = fb[rr.x * 4 + inl], r1 = fb[rr.y * 4 + inl];
            bool r2 = fb[rr.z * 4 + inl], r3 = fb[rr.w * 4 + inl];
            bool c0 = fb[cc.x * 4 + inl], c1 = fb[cc.y * 4 + inl];
            bool c2 = fb[cc.z * 4 + inl], c3 = fb[cc.w * 4 + inl];
            if (r0) fb[cc.x * 4 + outl] = 1;
            if (r1) fb[cc.y * 4 + outl] = 1;
            if (r2) fb[cc.z * 4 + outl] = 1;
            if (r3) fb[cc.w * 4 + outl] = 1;
            if (c0) fb[rr.x * 4 + outl] = 1;
            if (c1) fb[rr.y * 4 + outl] = 1;
            if (c2) fb[rr.z * 4 + outl] = 1;
            if (c3) fb[rr.w * 4 + outl] = 1;
        }
        if (tid == 0) {
            for (int j = n4 * 4; j < E; j++) {
                if (fb[r[j] * 4 + inl]) fb[c[j] * 4 + outl] = 1;
                if (fb[c[j] * 4 + inl]) fb[r[j] * 4 + outl] = 1;
            }
        }
        gbar(bar, FB_BLOCKS * (2 + pass));
    }

    // ---- Phase 3: frontier-filtered scatter + list compaction (independent) ----
    for (int i = tid; i < n4; i += NT) {
        int4 rr = __ldg(r4 + i);
        int4 cc = __ldg(c4 + i);
        float4 vv = __ldg(v4 + i);
        unsigned int fr0 = flags[rr.x], fc0 = flags[cc.x];
        unsigned int fr1 = flags[rr.y], fc1 = flags[cc.y];
        unsigned int fr2 = flags[rr.z], fc2 = flags[cc.z];
        unsigned int fr3 = flags[rr.w], fc3 = flags[cc.w];
        if (fr0) { int p = atomicAdd(&wpos[rr.x], 1); csr[p] = make_int2(cc.x, __float_as_int(vv.x)); }
        if (fc0) { int p = atomicAdd(&wpos[cc.x], 1); csr[p] = make_int2(rr.x, __float_as_int(vv.x)); }
        if (fr1) { int p = atomicAdd(&wpos[rr.y], 1); csr[p] = make_int2(cc.y, __float_as_int(vv.y)); }
        if (fc1) { int p = atomicAdd(&wpos[cc.y], 1); csr[p] = make_int2(rr.y, __float_as_int(vv.y)); }
        if (fr2) { int p = atomicAdd(&wpos[rr.z], 1); csr[p] = make_int2(cc.z, __float_as_int(vv.z)); }
        if (fc2) { int p = atomicAdd(&wpos[cc.z], 1); csr[p] = make_int2(rr.z, __float_as_int(vv.z)); }
        if (fr3) { int p = atomicAdd(&wpos[rr.w], 1); csr[p] = make_int2(cc.w, __float_as_int(vv.w)); }
        if (fc3) { int p = atomicAdd(&wpos[cc.w], 1); csr[p] = make_int2(rr.w, __float_as_int(vv.w)); }
    }
    if (tid == 0) {
        for (int j = n4 * 4; j < E; j++) {
            int rj = r[j], cj = c[j]; float vj = v[j];
            if (flags[rj]) { int p = atomicAdd(&wpos[rj], 1); csr[p] = make_int2(cj, __float_as_int(vj)); }
            if (flags[cj]) { int p = atomicAdd(&wpos[cj], 1); csr[p] = make_int2(rj, __float_as_int(vj)); }
        }
    }
    // compaction of levels 1,2 (warp-aggregated), grid-stride over nodes
    int lane = threadIdx.x & 31;
    for (int base = tid & ~31; base < NN; base += NT) {
        int rr = base + lane;
        unsigned int f = (rr < NN) ? flags[rr] : 0u;
#pragma unroll
        for (int l = 1; l <= 2; l++) {
            bool p = (f >> (8 * l)) & 1u;
            unsigned int m = __ballot_sync(0xffffffffu, p);
            if (m) {
                int leader = __ffs(m) - 1;
                int bse = 0;
                if (lane == leader) bse = atomicAdd(cnt + l, __popc(m));
                bse = __shfl_sync(0xffffffffu, bse, leader);
                if (p) lists[(l - 1) * NN + bse + __popc(m & ((1u << lane) - 1u))] = rr;
            }
        }
    }
}

// ============ layer-1 SpMM: masked x0 gather via per-row sizes ============
__global__ void spmm_fused_k(const int* __restrict__ list, const int* __restrict__ cntp,
                             const int* __restrict__ wpos, const int2* __restrict__ csr,
                             const int* __restrict__ sizes,
                             const float4* __restrict__ ue, const float4* __restrict__ ie,
                             float4* __restrict__ y) {
    int n16 = *cntp * DV;
    for (int t = blockIdx.x * blockDim.x + threadIdx.x; t < n16;
         t += gridDim.x * blockDim.x) {
        int r = list[t >> 4];
        int lane = t & 15;
        int k = lane << 2;
        int s = r * STRIDE;
        int e = __ldg(wpos + r);
        float4 acc = make_float4(0.f, 0.f, 0.f, 0.f);
        int j = s;
        for (; j + 2 <= e; j += 2) {
            int2 q0 = __ldg(csr + j);
            int2 q1 = __ldg(csr + j + 1);
            float v0 = __int_as_float(q0.y), v1 = __int_as_float(q1.y);
            int i0 = (q0.x < NU) ? q0.x * DV + lane : (q0.x - NU) * DV + lane;
            int i1 = (q1.x < NU) ? q1.x * DV + lane : (q1.x - NU) * DV + lane;
            float4 x0 = (q0.x < NU) ? __ldg(ue + i0) : __ldg(ie + i0);
            float4 x1 = (q1.x < NU) ? __ldg(ue + i1) : __ldg(ie + i1);
            int s0 = __ldg(sizes + q0.x);
            int s1 = __ldg(sizes + q1.x);
            if (k + 0 < s0) acc.x += v0 * x0.x;
            if (k + 1 < s0) acc.y += v0 * x0.y;
            if (k + 2 < s0) acc.z += v0 * x0.z;
            if (k + 3 < s0) acc.w += v0 * x0.w;
            if (k + 0 < s1) acc.x += v1 * x1.x;
            if (k + 1 < s1) acc.y += v1 * x1.y;
            if (k + 2 < s1) acc.z += v1 * x1.z;
            if (k + 3 < s1) acc.w += v1 * x1.w;
        }
        if (j < e) {
            int2 q = __ldg(csr + j);
            float v = __int_as_float(q.y);
            int i0 = (q.x < NU) ? q.x * DV + lane : (q.x - NU) * DV + lane;
            float4 x = (q.x < NU) ? __ldg(ue + i0) : __ldg(ie + i0);
            int s0 = __ldg(sizes + q.x);
            if (k + 0 < s0) acc.x += v * x.x;
            if (k + 1 < s0) acc.y += v * x.y;
            if (k + 2 < s0) acc.z += v * x.z;
            if (k + 3 < s0) acc.w += v * x.w;
        }
        y[(size_t)r * DV + lane] = acc;
    }
}

// ============ layer 2: strided CSR SpMM ============
__global__ void spmm_k(const int* __restrict__ list, const int* __restrict__ cntp,
                       const int* __restrict__ wpos, const int2* __restrict__ csr,
                       const float4* __restrict__ x, float4* __restrict__ y) {
    int n16 = *cntp * DV;
    for (int t = blockIdx.x * blockDim.x + threadIdx.x; t < n16;
         t += gridDim.x * blockDim.x) {
        int r = list[t >> 4];
        int lane = t & 15;
        int s = r * STRIDE;
        int e = __ldg(wpos + r);
        float4 acc = make_float4(0.f, 0.f, 0.f, 0.f);
        int j = s;
        for (; j + 2 <= e; j += 2) {
            int2 q0 = __ldg(csr + j);
            int2 q1 = __ldg(csr + j + 1);
            float v0 = __int_as_float(q0.y), v1 = __int_as_float(q1.y);
            float4 x0 = __ldg(x + (size_t)q0.x * DV + lane);
            float4 x1 = __ldg(x + (size_t)q1.x * DV + lane);
            acc.x += v0 * x0.x + v1 * x1.x;
            acc.y += v0 * x0.y + v1 * x1.y;
            acc.z += v0 * x0.z + v1 * x1.z;
            acc.w += v0 * x0.w + v1 * x1.w;
        }
        if (j < e) {
            int2 q = __ldg(csr + j);
            float v = __int_as_float(q.y);
            float4 xv = __ldg(x + (size_t)q.x * DV + lane);
            acc.x += v * xv.x;
            acc.y += v * xv.y;
            acc.z += v * xv.z;
            acc.w += v * xv.w;
        }
        y[(size_t)r * DV + lane] = acc;
    }
}

// ============ fused layer-3 SpMM + final accumulate ============
__global__ void final_fused_k(const float4* __restrict__ l1, const float4* __restrict__ l2,
                              const int* __restrict__ wpos, const int2* __restrict__ csr,
                              const int* __restrict__ users, const int* __restrict__ pos,
                              const int* __restrict__ neg, float4* __restrict__ out) {
    int i = blockIdx.x * blockDim.x + threadIdx.x;
    if (i >= 3 * SEC) return;
    int sec = i / SEC;
    int rem = i - sec * SEC;
    int b = rem >> 4, lane = rem & 15;
    int row = (sec == 0) ? users[b] : (sec == 1 ? NU + pos[b] : NU + neg[b]);
    size_t o = (size_t)row * DV + lane;
    int s = row * STRIDE;
    int e = __ldg(wpos + row);
    float4 acc = make_float4(0.f, 0.f, 0.f, 0.f);
    int j = s;
    for (; j + 2 <= e; j += 2) {
        int2 q0 = __ldg(csr + j);
        int2 q1 = __ldg(csr + j + 1);
        float v0 = __int_as_float(q0.y), v1 = __int_as_float(q1.y);
        float4 x0 = __ldg(l2 + (size_t)q0.x * DV + lane);
        float4 x1 = __ldg(l2 + (size_t)q1.x * DV + lane);
        acc.x += v0 * x0.x + v1 * x1.x;
        acc.y += v0 * x0.y + v1 * x1.y;
        acc.z += v0 * x0.z + v1 * x1.z;
        acc.w += v0 * x0.w + v1 * x1.w;
    }
    if (j < e) {
        int2 q = __ldg(csr + j);
        float v = __int_as_float(q.y);
        float4 xv = __ldg(l2 + (size_t)q.x * DV + lane);
        acc.x += v * xv.x;
        acc.y += v * xv.y;
        acc.z += v * xv.z;
        acc.w += v * xv.w;
    }
    float4 a = out[i], v1 = l1[o], v2 = l2[o];
    float4 r;
    r.x = (a.x + v1.x + v2.x + acc.x) * 0.25f;
    r.y = (a.y + v1.y + v2.y + acc.y) * 0.25f;
    r.z = (a.z + v1.z + v2.z + acc.z) * 0.25f;
    r.w = (a.w + v1.w + v2.w + acc.w) * 0.25f;
    out[i] = r;
}

extern "C" void kernel_launch(void* const* d_in, const int* in_sizes, int n_in,
                              void* d_out, int out_size) {
    const float* ue   = (const float*)d_in[0];
    const float* ie   = (const float*)d_in[1];
    const int*   um   = (const int*)  d_in[2];
    const int*   im   = (const int*)  d_in[3];
    const int*   rows = (const int*)  d_in[4];
    const int*   cols = (const int*)  d_in[5];
    const float* vals = (const float*)d_in[6];
    const int*   users= (const int*)  d_in[7];
    const int*   pos  = (const int*)  d_in[8];
    const int*   neg  = (const int*)  d_in[9];
    int nnz = in_sizes[4];
    int E = nnz / 2;          // COO is mirrored [u->it ; it->u]
    float* out = (float*)d_out;

    float *bufA, *bufB;
    int2* csr;
    int *wpos, *sizes, *lists, *blob;
    cudaGetSymbolAddress((void**)&bufA, g_bufA);
    cudaGetSymbolAddress((void**)&bufB, g_bufB);
    cudaGetSymbolAddress((void**)&csr, g_scsr);
    cudaGetSymbolAddress((void**)&wpos, g_wpos);
    cudaGetSymbolAddress((void**)&sizes, g_sizes);
    cudaGetSymbolAddress((void**)&lists, g_lists);
    cudaGetSymbolAddress((void**)&blob, g_blob);

    unsigned int* flags = (unsigned int*)blob;
    int* cnt = blob + CNT_OFF;
    unsigned int* bar = (unsigned int*)(blob + BAR_OFF);

    // lazily-created aux stream + events (host-side handles only)
    static cudaStream_t s2 = nullptr;
    static cudaEvent_t evFork = nullptr, evSizes = nullptr, evInit = nullptr;
    if (s2 == nullptr) {
        cudaStreamCreateWithFlags(&s2, cudaStreamNonBlocking);
        cudaEventCreateWithFlags(&evFork, cudaEventDisableTiming);
        cudaEventCreateWithFlags(&evSizes, cudaEventDisableTiming);
        cudaEventCreateWithFlags(&evInit, cudaEventDisableTiming);
    }

    const int TPB = 256;
    const int gBlocks = (3 * SEC + TPB - 1) / TPB;
    const int n4 = E / 4;
    const int szBlocks = (NN * DV + TPB - 1) / TPB;
    const int ioBlocks = (3 * SEC / 2 + TPB - 1) / TPB;
    const int GS = 4096;

    // per-launch memset resets flags, cnt, and the grid-barrier counter
    cudaMemsetAsync(blob, 0, BLOB_INTS * sizeof(int));
    cudaEventRecord(evFork, 0);
    cudaStreamWaitEvent(s2, evFork, 0);

    // ---- chain C (s2): sizes (gates spmm1), then heavy out-init (gates only final) ----
    sizes_k<<<szBlocks, TPB, 0, s2>>>((const int4*)um, (const int4*)im, sizes);
    cudaEventRecord(evSizes, s2);
    init_out_k<<<ioBlocks, TPB, 0, s2>>>((const float4*)ue, (const float4*)ie,
                                         (const int4*)um, (const int4*)im,
                                         users, pos, neg, (float4*)out);
    cudaEventRecord(evInit, s2);

    // ---- chain A (default): single fused frontier pipeline ----
    frontier_fused_k<<<FB_BLOCKS, FB_TPB>>>((const int4*)rows, (const int4*)cols,
                                            (const float4*)vals, rows, cols, vals,
                                            users, pos, neg, flags, wpos, csr,
                                            lists, cnt, bar, n4, E);

    cudaStreamWaitEvent(0, evSizes, 0);

    // ---- layers 1,2 then fused layer-3 + accumulate ----
    spmm_fused_k<<<GS, TPB>>>(lists + 0 * NN, cnt + 1, wpos, csr, sizes,
                              (const float4*)ue, (const float4*)ie, (float4*)bufA);
    spmm_k<<<GS, TPB>>>(lists + 1 * NN, cnt + 2, wpos, csr,
                        (const float4*)bufA, (float4*)bufB);
    cudaStreamWaitEvent(0, evInit, 0);
    final_fused_k<<<gBlocks, TPB>>>((const float4*)bufA, (const float4*)bufB,
                                    wpos, csr, users, pos, neg, (float4*)out);
}